// round 7
// baseline (speedup 1.0000x reference)
#include <cuda_runtime.h>
#include <cstdint>

#define EN 500000
#define NN 100000
#define DD 128
#define LN_EPS 1e-5f
#define TILE_M 128
#define NCTAS 3907
#define THREADS 256

// SMEM map (bytes into dynamic smem)
#define SM_B1    0
#define SM_B2    512
#define SM_GAMMA 1024
#define SM_BETA  1536
#define SM_SRC   2048
#define SM_DST   2560
#define SM_BUF   4096      // GEMM1: A0,A1 (2x16KB); then overlaid as H[128][128] (64KB)
#define SM_RED   69632     // 2KB reductions
#define SMEM_TOTAL 71680

__device__ int g_idx64;
__device__ float g_w1frag[24 * 16 * 32 * 4];  // [(u=kc*2+kp)*16+ntile]*32+lane, float4 per lane
__device__ float g_w2frag[128 * 128];         // [(kp*16+ntile)*32+lane]*4+j

// ---------------- helpers ----------------
__device__ __forceinline__ uint32_t smem_u32(const void* p) {
    uint32_t a;
    asm("{ .reg .u64 t; cvta.to.shared.u64 t, %1; cvt.u32.u64 %0, t; }" : "=r"(a) : "l"(p));
    return a;
}
__device__ __forceinline__ float tf32_rn(float x) {
    float r; asm("cvt.rna.tf32.f32 %0, %1;" : "=f"(r) : "f"(x)); return r;
}
__device__ __forceinline__ void ldsm4(uint32_t& d0, uint32_t& d1, uint32_t& d2, uint32_t& d3,
                                      uint32_t addr) {
    asm volatile("ldmatrix.sync.aligned.m8n8.x4.shared.b16 {%0,%1,%2,%3}, [%4];"
        : "=r"(d0), "=r"(d1), "=r"(d2), "=r"(d3) : "r"(addr));
}
__device__ __forceinline__ void mma_tf32(float* c, uint32_t a0, uint32_t a1, uint32_t a2,
                                         uint32_t a3, uint32_t b0, uint32_t b1) {
    asm volatile("mma.sync.aligned.m16n8k8.row.col.f32.tf32.tf32.f32 "
        "{%0,%1,%2,%3},{%4,%5,%6,%7},{%8,%9},{%0,%1,%2,%3};"
        : "+f"(c[0]), "+f"(c[1]), "+f"(c[2]), "+f"(c[3])
        : "r"(a0), "r"(a1), "r"(a2), "r"(a3), "r"(b0), "r"(b1));
}

// ---------------- prep kernel (detect + fragment images) ----------------
__global__ void prep_weights_kernel(const float* __restrict__ w1,
                                    const float* __restrict__ w2,
                                    const void* __restrict__ src) {
    int i = blockIdx.x * blockDim.x + threadIdx.x;   // 0..114687
    if (i == 0) {
        const long long* p = (const long long*)src;
        int ok = 1;
        #pragma unroll
        for (int t = 0; t < 32; t++) {
            long long v = p[t];
            if (v < 0 || v >= (long long)NN) ok = 0;
        }
        g_idx64 = ok;
    }
    if (i < 49152) {
        // w1 fragment image: value mma expects in reg j of `lane` for unit u, ntile
        int j = i & 3, lane = (i >> 2) & 31, ntile = (i >> 7) & 15, u = i >> 11;  // u: 0..23
        int k = u * 16 + 4 * j + (lane & 3);
        int n = ntile * 8 + (lane >> 2);
        g_w1frag[i] = tf32_rn(w1[(size_t)k * 128 + n]);
    } else if (i < 49152 + 65536) {
        int t = i - 49152;
        int j = t & 3, lane = (t >> 2) & 31, ntile = (t >> 7) & 15, kp = t >> 11;
        int k = kp * 16 + 4 * j + (lane & 3);
        int n = ntile * 8 + (lane >> 2);
        g_w2frag[t] = tf32_rn(w2[(size_t)k * 128 + n]);
    }
}

__global__ void copy_nfeat_kernel(const float4* __restrict__ in,
                                  float4* __restrict__ out, int n4) {
    int i = blockIdx.x * blockDim.x + threadIdx.x;
    if (i < n4) out[i] = in[i];
}

// ---------------- main fused kernel ----------------
__global__ __launch_bounds__(THREADS, 2) void fused_mma_kernel(
    const float* __restrict__ efeat, const float* __restrict__ nfeat,
    const void* __restrict__ src_raw, const void* __restrict__ dst_raw,
    const float* __restrict__ b1, const float* __restrict__ b2,
    const float* __restrict__ gamma, const float* __restrict__ beta,
    float* __restrict__ out)
{
    extern __shared__ __align__(1024) char smem[];
    const uint32_t sb = smem_u32(smem);
    const int tid = threadIdx.x;
    const int wid = tid >> 5, lane = tid & 31;
    const int wr = wid & 3, wc = wid >> 2;
    const int e0 = blockIdx.x * TILE_M;
    const int valid = min(TILE_M, EN - e0);

    if (tid < 128) {
        ((float*)(smem + SM_B1))[tid]    = b1[tid];
        ((float*)(smem + SM_B2))[tid]    = b2[tid];
        ((float*)(smem + SM_GAMMA))[tid] = gamma[tid];
        ((float*)(smem + SM_BETA))[tid]  = beta[tid];
        int e = min(e0 + tid, EN - 1);
        int s, d;
        if (g_idx64) {
            s = (int)((const long long*)src_raw)[e];
            d = (int)((const long long*)dst_raw)[e];
        } else {
            s = ((const int*)src_raw)[e];
            d = ((const int*)dst_raw)[e];
        }
        ((int*)(smem + SM_SRC))[tid] = s;
        ((int*)(smem + SM_DST))[tid] = d;
    }
    __syncthreads();

    const int* ssrc = (const int*)(smem + SM_SRC);
    const int* sdst = (const int*)(smem + SM_DST);
    float* Abuf[2] = { (float*)(smem + SM_BUF), (float*)(smem + SM_BUF + 16384) };
    uint32_t Abu[2] = { sb + SM_BUF, sb + SM_BUF + 16384 };

    const int r_base = tid >> 3;
    const int j_ld   = tid & 7;

    float4 v[4];
    auto ldgA = [&](int kc) {
        const int colb = ((kc & 3) << 5) + (j_ld << 2);
        #pragma unroll
        for (int t = 0; t < 4; t++) {
            int r = r_base + t * 32;
            const float* rp;
            if (kc < 4)      rp = efeat + (size_t)min(e0 + r, EN - 1) * DD;
            else if (kc < 8) rp = nfeat + (size_t)ssrc[r] * DD;
            else             rp = nfeat + (size_t)sdst[r] * DD;
            v[t] = *(const float4*)(rp + colb);
        }
    };
    auto stsA = [&](float* Ab) {
        #pragma unroll
        for (int t = 0; t < 4; t++) {
            int r = r_base + t * 32;
            float4 w;
            w.x = tf32_rn(v[t].x); w.y = tf32_rn(v[t].y);
            w.z = tf32_rn(v[t].z); w.w = tf32_rn(v[t].w);
            *(float4*)(Ab + r * 32 + ((j_ld ^ (r & 7)) << 2)) = w;
        }
    };

    // ======== GEMM1: K=384 in 12 chunks of 32, A double-buffered, B via LDG frags ========
    const float4* w1f = (const float4*)g_w1frag;
    {
        float acc[2][8][4];
        #pragma unroll
        for (int mt = 0; mt < 2; mt++)
            #pragma unroll
            for (int nt = 0; nt < 8; nt++)
                #pragma unroll
                for (int q = 0; q < 4; q++) acc[mt][nt][q] = 0.f;

        ldgA(0); stsA(Abuf[0]);
        ldgA(1);
        for (int kc = 0; kc < 12; kc++) {
            const int s = kc & 1;
            __syncthreads();                // buf[s] ready; prior reads of buf[1-s] done
            if (kc + 1 < 12) {
                stsA(Abuf[1 - s]);
                if (kc + 2 < 12) ldgA(kc + 2);
            }
            #pragma unroll
            for (int kp = 0; kp < 2; kp++) {
                // B fragments straight from L2-resident image
                float4 bf[8];
                #pragma unroll
                for (int nt = 0; nt < 8; nt++)
                    bf[nt] = w1f[((kc * 2 + kp) * 16 + wc * 8 + nt) * 32 + lane];
                uint32_t a[2][2][4];
                #pragma unroll
                for (int mt = 0; mt < 2; mt++)
                    #pragma unroll
                    for (int ksl = 0; ksl < 2; ksl++) {
                        int ks = kp * 2 + ksl;
                        int row = wr * 32 + mt * 16 + (lane & 15);
                        int g = ks * 2 + (lane >> 4);
                        ldsm4(a[mt][ksl][0], a[mt][ksl][1], a[mt][ksl][2], a[mt][ksl][3],
                              Abu[s] + 4 * (row * 32 + ((g ^ (row & 7)) << 2)));
                    }
                #pragma unroll
                for (int nt = 0; nt < 8; nt++)
                    #pragma unroll
                    for (int mt = 0; mt < 2; mt++) {
                        mma_tf32(acc[mt][nt], a[mt][0][0], a[mt][0][1], a[mt][0][2], a[mt][0][3],
                                 __float_as_uint(bf[nt].x), __float_as_uint(bf[nt].y));
                        mma_tf32(acc[mt][nt], a[mt][1][0], a[mt][1][1], a[mt][1][2], a[mt][1][3],
                                 __float_as_uint(bf[nt].z), __float_as_uint(bf[nt].w));
                    }
            }
        }
        __syncthreads();   // S1: A bufs free -> become H

        // ======== Epilogue 1: +b1, SiLU, tf32-round -> H (overlay on bufs) ========
        const float* sb1 = (const float*)(smem + SM_B1);
        const int q = lane & 3, rq = lane >> 2;
        #pragma unroll
        for (int mt = 0; mt < 2; mt++) {
            int rl = wr * 32 + mt * 16 + rq, rh = rl + 8;
            #pragma unroll
            for (int nt = 0; nt < 8; nt++) {
                int c0 = wc * 64 + nt * 8 + 2 * q;
                float x0 = acc[mt][nt][0] + sb1[c0];
                float x1 = acc[mt][nt][1] + sb1[c0 + 1];
                float x2 = acc[mt][nt][2] + sb1[c0];
                float x3 = acc[mt][nt][3] + sb1[c0 + 1];
                float2 lo, hi;
                lo.x = tf32_rn(__fdividef(x0, 1.f + __expf(-x0)));
                lo.y = tf32_rn(__fdividef(x1, 1.f + __expf(-x1)));
                hi.x = tf32_rn(__fdividef(x2, 1.f + __expf(-x2)));
                hi.y = tf32_rn(__fdividef(x3, 1.f + __expf(-x3)));
                int g = c0 >> 2, cm = c0 & 3;
                *(float2*)(smem + SM_BUF + 4 * (rl * 128 + ((g ^ (rl & 7)) << 2) + cm)) = lo;
                *(float2*)(smem + SM_BUF + 4 * (rh * 128 + ((g ^ (rh & 7)) << 2) + cm)) = hi;
            }
        }
    }   // acc dies here
    __syncthreads();       // S2: H complete

    // ======== GEMM2: D2 = H[128,128] @ w2 ; B frags via LDG ========
    float acc2[2][8][4];
    #pragma unroll
    for (int mt = 0; mt < 2; mt++)
        #pragma unroll
        for (int nt = 0; nt < 8; nt++)
            #pragma unroll
            for (int q = 0; q < 4; q++) acc2[mt][nt][q] = 0.f;

    const float4* w2f = (const float4*)g_w2frag;
    #pragma unroll
    for (int kp = 0; kp < 8; kp++) {
        float4 bf[8];
        #pragma unroll
        for (int nt = 0; nt < 8; nt++)
            bf[nt] = w2f[(kp * 16 + wc * 8 + nt) * 32 + lane];
        uint32_t a[2][2][4];
        #pragma unroll
        for (int mt = 0; mt < 2; mt++)
            #pragma unroll
            for (int ksl = 0; ksl < 2; ksl++) {
                int ks = kp * 2 + ksl;
                int row = wr * 32 + mt * 16 + (lane & 15);
                int g = ks * 2 + (lane >> 4);
                ldsm4(a[mt][ksl][0], a[mt][ksl][1], a[mt][ksl][2], a[mt][ksl][3],
                      sb + SM_BUF + 4 * (row * 128 + ((g ^ (row & 7)) << 2)));
            }
        #pragma unroll
        for (int nt = 0; nt < 8; nt++)
            #pragma unroll
            for (int mt = 0; mt < 2; mt++) {
                mma_tf32(acc2[mt][nt], a[mt][0][0], a[mt][0][1], a[mt][0][2], a[mt][0][3],
                         __float_as_uint(bf[nt].x), __float_as_uint(bf[nt].y));
                mma_tf32(acc2[mt][nt], a[mt][1][0], a[mt][1][1], a[mt][1][2], a[mt][1][3],
                         __float_as_uint(bf[nt].z), __float_as_uint(bf[nt].w));
            }
    }

    // ======== Epilogue 2: +b2, LayerNorm, residual, direct STG ========
    {
        const float* sb2 = (const float*)(smem + SM_B2);
        const int q = lane & 3, rq = lane >> 2;
        float s1[2][2], s2[2][2];
        #pragma unroll
        for (int mt = 0; mt < 2; mt++) { s1[mt][0] = s1[mt][1] = s2[mt][0] = s2[mt][1] = 0.f; }
        #pragma unroll
        for (int mt = 0; mt < 2; mt++)
            #pragma unroll
            for (int nt = 0; nt < 8; nt++) {
                int c0 = wc * 64 + nt * 8 + 2 * q;
                float y0 = acc2[mt][nt][0] + sb2[c0];
                float y1 = acc2[mt][nt][1] + sb2[c0 + 1];
                float y2 = acc2[mt][nt][2] + sb2[c0];
                float y3 = acc2[mt][nt][3] + sb2[c0 + 1];
                acc2[mt][nt][0] = y0; acc2[mt][nt][1] = y1;
                acc2[mt][nt][2] = y2; acc2[mt][nt][3] = y3;
                s1[mt][0] += y0 + y1; s2[mt][0] += y0 * y0 + y1 * y1;
                s1[mt][1] += y2 + y3; s2[mt][1] += y2 * y2 + y3 * y3;
            }
        #pragma unroll
        for (int mt = 0; mt < 2; mt++)
            #pragma unroll
            for (int h = 0; h < 2; h++) {
                s1[mt][h] += __shfl_xor_sync(0xffffffffu, s1[mt][h], 1);
                s1[mt][h] += __shfl_xor_sync(0xffffffffu, s1[mt][h], 2);
                s2[mt][h] += __shfl_xor_sync(0xffffffffu, s2[mt][h], 1);
                s2[mt][h] += __shfl_xor_sync(0xffffffffu, s2[mt][h], 2);
            }
        float* red1 = (float*)(smem + SM_RED);
        float* red2 = red1 + 256;
        if (q == 0) {
            #pragma unroll
            for (int mt = 0; mt < 2; mt++) {
                int rl = wr * 32 + mt * 16 + rq;
                red1[wc * 128 + rl]     = s1[mt][0];
                red2[wc * 128 + rl]     = s2[mt][0];
                red1[wc * 128 + rl + 8] = s1[mt][1];
                red2[wc * 128 + rl + 8] = s2[mt][1];
            }
        }
        __syncthreads();   // S3: red ready
        const float* sg  = (const float*)(smem + SM_GAMMA);
        const float* sbt = (const float*)(smem + SM_BETA);
        #pragma unroll
        for (int mt = 0; mt < 2; mt++)
            #pragma unroll
            for (int h = 0; h < 2; h++) {
                int r = wr * 32 + mt * 16 + rq + h * 8;
                float S1 = red1[r] + red1[128 + r];
                float S2 = red2[r] + red2[128 + r];
                float mu = S1 * (1.f / 128.f);
                float rs = rsqrtf(S2 * (1.f / 128.f) - mu * mu + LN_EPS);
                if (r < valid) {
                    const size_t e = (size_t)(e0 + r);
                    #pragma unroll
                    for (int nt = 0; nt < 8; nt++) {
                        int c0 = wc * 64 + nt * 8 + 2 * q;
                        float2 ef = *(const float2*)(efeat + e * DD + c0);
                        float2 o;
                        o.x = (acc2[mt][nt][2 * h]     - mu) * rs * sg[c0]     + sbt[c0]     + ef.x;
                        o.y = (acc2[mt][nt][2 * h + 1] - mu) * rs * sg[c0 + 1] + sbt[c0 + 1] + ef.y;
                        *(float2*)(out + e * DD + c0) = o;
                    }
                }
            }
    }
}

extern "C" void kernel_launch(void* const* d_in, const int* in_sizes, int n_in,
                              void* d_out, int out_size) {
    const float* efeat = (const float*)d_in[0];
    const float* nfeat = (const float*)d_in[1];
    const void*  src   = d_in[2];
    const void*  dst   = d_in[3];
    const float* w1    = (const float*)d_in[4];
    const float* b1    = (const float*)d_in[5];
    const float* w2    = (const float*)d_in[6];
    const float* b2    = (const float*)d_in[7];
    const float* gamma = (const float*)d_in[8];
    const float* beta  = (const float*)d_in[9];
    float* out = (float*)d_out;

    cudaFuncSetAttribute(fused_mma_kernel,
                         cudaFuncAttributeMaxDynamicSharedMemorySize, SMEM_TOTAL);

    prep_weights_kernel<<<448, 256>>>(w1, w2, src);
    const long long need = (long long)EN * DD + (long long)NN * DD;
    if ((long long)out_size >= need) {
        int n4 = NN * DD / 4;
        copy_nfeat_kernel<<<(n4 + 255) / 256, 256>>>(
            (const float4*)nfeat, (float4*)(out + (size_t)EN * DD), n4);
    }
    fused_mma_kernel<<<NCTAS, THREADS, SMEM_TOTAL>>>(
        efeat, nfeat, src, dst, b1, b2, gamma, beta, out);
}

// round 9
// speedup vs baseline: 1.2656x; 1.2656x over previous
#include <cuda_runtime.h>
#include <cstdint>

#define EN 500000
#define NN 100000
#define DD 128
#define LN_EPS 1e-5f
#define TILE_M 128
#define NCTAS 3907
#define THREADS 256

// SMEM map (bytes into dynamic smem)
#define SM_B1    0
#define SM_B2    512
#define SM_GAMMA 1024
#define SM_BETA  1536
#define SM_SRC   2048
#define SM_DST   2560
#define SM_BUF   4096      // 64KB: GEMM1 A0,A1,B0,B1 (4x16KB); then overlaid as H[128][128]
#define SM_RED   69632     // 2KB reductions
#define SMEM_TOTAL 71680

__device__ int g_idx64;
__device__ float g_w1img[12 * 4096];    // [chunk][n=128][k=32], tf32-rounded, granule-swizzled
__device__ float g_w2frag[128 * 128];   // fragment-ordered w2: [(kp*16+ntile)*32+lane]*4+j

// ---------------- helpers ----------------
__device__ __forceinline__ uint32_t smem_u32(const void* p) {
    uint32_t a;
    asm("{ .reg .u64 t; cvta.to.shared.u64 t, %1; cvt.u32.u64 %0, t; }" : "=r"(a) : "l"(p));
    return a;
}
__device__ __forceinline__ float tf32_rn(float x) {
    float r; asm("cvt.rna.tf32.f32 %0, %1;" : "=f"(r) : "f"(x)); return r;
}
__device__ __forceinline__ void cp16(uint32_t dst, const void* src) {
    asm volatile("cp.async.cg.shared.global [%0], [%1], 16;"
        :: "r"(dst), "l"(__cvta_generic_to_global(src)));
}
__device__ __forceinline__ void cp_commit() { asm volatile("cp.async.commit_group;"); }
__device__ __forceinline__ void cp_wait0()  { asm volatile("cp.async.wait_group 0;"); }

__device__ __forceinline__ void ldsm4(uint32_t& d0, uint32_t& d1, uint32_t& d2, uint32_t& d3,
                                      uint32_t addr) {
    asm volatile("ldmatrix.sync.aligned.m8n8.x4.shared.b16 {%0,%1,%2,%3}, [%4];"
        : "=r"(d0), "=r"(d1), "=r"(d2), "=r"(d3) : "r"(addr));
}
__device__ __forceinline__ void mma_tf32(float* c, uint32_t a0, uint32_t a1, uint32_t a2,
                                         uint32_t a3, uint32_t b0, uint32_t b1) {
    asm volatile("mma.sync.aligned.m16n8k8.row.col.f32.tf32.tf32.f32 "
        "{%0,%1,%2,%3},{%4,%5,%6,%7},{%8,%9},{%0,%1,%2,%3};"
        : "+f"(c[0]), "+f"(c[1]), "+f"(c[2]), "+f"(c[3])
        : "r"(a0), "r"(a1), "r"(a2), "r"(a3), "r"(b0), "r"(b1));
}

// ---------------- prep kernel (detect + weight images) ----------------
__global__ void prep_weights_kernel(const float* __restrict__ w1,
                                    const float* __restrict__ w2,
                                    const void* __restrict__ src) {
    int i = blockIdx.x * blockDim.x + threadIdx.x;   // 0..114687
    if (i == 0) {
        const long long* p = (const long long*)src;
        int ok = 1;
        #pragma unroll
        for (int t = 0; t < 32; t++) {
            long long v = p[t];
            if (v < 0 || v >= (long long)NN) ok = 0;
        }
        g_idx64 = ok;
    }
    if (i < 49152) {
        // w1 image: n-major, granule-swizzled (ldsm path)
        int chunk = i >> 12, idx = i & 4095;
        int k = idx >> 7, n = idx & 127;
        float v = tf32_rn(w1[(size_t)(chunk * 32 + k) * 128 + n]);
        g_w1img[chunk * 4096 + n * 32 + (((k >> 2) ^ (n & 7)) << 2) + (k & 3)] = v;
    } else if (i < 49152 + 65536) {
        // w2 fragment image: value ldmatrix would deliver to reg j of `lane`
        int t = i - 49152;
        int j = t & 3, lane = (t >> 2) & 31, ntile = (t >> 7) & 15, kp = t >> 11;
        int k = kp * 16 + 4 * j + (lane & 3);
        int n = ntile * 8 + (lane >> 2);
        g_w2frag[t] = tf32_rn(w2[(size_t)k * 128 + n]);
    }
}

__global__ void copy_nfeat_kernel(const float4* __restrict__ in,
                                  float4* __restrict__ out, int n4) {
    int i = blockIdx.x * blockDim.x + threadIdx.x;
    if (i < n4) out[i] = in[i];
}

// ---------------- main fused kernel ----------------
__global__ __launch_bounds__(THREADS, 2) void fused_mma_kernel(
    const float* __restrict__ efeat, const float* __restrict__ nfeat,
    const void* __restrict__ src_raw, const void* __restrict__ dst_raw,
    const float* __restrict__ b1, const float* __restrict__ b2,
    const float* __restrict__ gamma, const float* __restrict__ beta,
    float* __restrict__ out)
{
    extern __shared__ __align__(1024) char smem[];
    const uint32_t sb = smem_u32(smem);
    const int tid = threadIdx.x;
    const int wid = tid >> 5, lane = tid & 31;
    const int wr = wid & 3, wc = wid >> 2;
    const int e0 = blockIdx.x * TILE_M;
    const int valid = min(TILE_M, EN - e0);

    if (tid < 128) {
        ((float*)(smem + SM_B1))[tid]    = b1[tid];
        ((float*)(smem + SM_B2))[tid]    = b2[tid];
        ((float*)(smem + SM_GAMMA))[tid] = gamma[tid];
        ((float*)(smem + SM_BETA))[tid]  = beta[tid];
        int e = min(e0 + tid, EN - 1);
        int s, d;
        if (g_idx64) {
            s = (int)((const long long*)src_raw)[e];
            d = (int)((const long long*)dst_raw)[e];
        } else {
            s = ((const int*)src_raw)[e];
            d = ((const int*)dst_raw)[e];
        }
        ((int*)(smem + SM_SRC))[tid] = s;
        ((int*)(smem + SM_DST))[tid] = d;
    }
    __syncthreads();

    const int* ssrc = (const int*)(smem + SM_SRC);
    const int* sdst = (const int*)(smem + SM_DST);
    uint32_t Abu[2] = { sb + SM_BUF, sb + SM_BUF + 16384 };
    uint32_t Bbu[2] = { sb + SM_BUF + 32768, sb + SM_BUF + 49152 };

    const int r_base = tid >> 3;
    const int j_ld   = tid & 7;

    // A chunk: raw cp.async gmem -> swizzled smem (HW mma truncates fp32->tf32)
    auto cpA = [&](int kc, uint32_t Ab) {
        const int colb = ((kc & 3) << 5) + (j_ld << 2);
        #pragma unroll
        for (int t = 0; t < 4; t++) {
            int r = r_base + t * 32;
            const float* rp;
            if (kc < 4)      rp = efeat + (size_t)min(e0 + r, EN - 1) * DD;
            else if (kc < 8) rp = nfeat + (size_t)ssrc[r] * DD;
            else             rp = nfeat + (size_t)sdst[r] * DD;
            cp16(Ab + r * 128 + ((j_ld ^ (r & 7)) << 4), rp + colb);
        }
    };
    auto cpB = [&](uint32_t dst, const float* src) {
        #pragma unroll
        for (int t = 0; t < 4; t++) {
            int i = tid + t * 256;
            cp16(dst + i * 16, (const void*)((const float4*)src + i));
        }
    };

    // ======== GEMM1: K=384 in 12 chunks of 32, double buffered via cp.async ========
    {
        float acc[2][8][4];
        #pragma unroll
        for (int mt = 0; mt < 2; mt++)
            #pragma unroll
            for (int nt = 0; nt < 8; nt++)
                #pragma unroll
                for (int q = 0; q < 4; q++) acc[mt][nt][q] = 0.f;

        cpA(0, Abu[0]); cpB(Bbu[0], g_w1img); cp_commit();
        for (int kc = 0; kc < 12; kc++) {
            const int s = kc & 1;
            cp_wait0();
            __syncthreads();            // chunk kc landed; all warps done with chunk kc-1 bufs
            if (kc + 1 < 12) {
                cpA(kc + 1, Abu[1 - s]);
                cpB(Bbu[1 - s], g_w1img + (kc + 1) * 4096);
                cp_commit();
            }
            #pragma unroll
            for (int kp = 0; kp < 2; kp++) {
                uint32_t a[2][2][4];
                #pragma unroll
                for (int mt = 0; mt < 2; mt++)
                    #pragma unroll
                    for (int ksl = 0; ksl < 2; ksl++) {
                        int ks = kp * 2 + ksl;
                        int row = wr * 32 + mt * 16 + (lane & 15);
                        int g = ks * 2 + (lane >> 4);
                        ldsm4(a[mt][ksl][0], a[mt][ksl][1], a[mt][ksl][2], a[mt][ksl][3],
                              Abu[s] + 4 * (row * 32 + ((g ^ (row & 7)) << 2)));
                    }
                #pragma unroll
                for (int nt = 0; nt < 8; nt++) {
                    int n = wc * 64 + nt * 8 + (lane & 7);
                    int g = kp * 4 + (lane >> 3);
                    uint32_t b0, b1r, b2r, b3;
                    ldsm4(b0, b1r, b2r, b3,
                          Bbu[s] + 4 * (n * 32 + ((g ^ (n & 7)) << 2)));
                    #pragma unroll
                    for (int mt = 0; mt < 2; mt++) {
                        mma_tf32(acc[mt][nt], a[mt][0][0], a[mt][0][1], a[mt][0][2], a[mt][0][3], b0, b1r);
                        mma_tf32(acc[mt][nt], a[mt][1][0], a[mt][1][1], a[mt][1][2], a[mt][1][3], b2r, b3);
                    }
                }
            }
        }
        __syncthreads();   // S1: bufs free -> become H

        // ======== Epilogue 1: +b1, SiLU, tf32-round -> H (overlay on bufs) ========
        const float* sb1 = (const float*)(smem + SM_B1);
        const int q = lane & 3, rq = lane >> 2;
        #pragma unroll
        for (int mt = 0; mt < 2; mt++) {
            int rl = wr * 32 + mt * 16 + rq, rh = rl + 8;
            #pragma unroll
            for (int nt = 0; nt < 8; nt++) {
                int c0 = wc * 64 + nt * 8 + 2 * q;
                float x0 = acc[mt][nt][0] + sb1[c0];
                float x1 = acc[mt][nt][1] + sb1[c0 + 1];
                float x2 = acc[mt][nt][2] + sb1[c0];
                float x3 = acc[mt][nt][3] + sb1[c0 + 1];
                float2 lo, hi;
                lo.x = tf32_rn(__fdividef(x0, 1.f + __expf(-x0)));
                lo.y = tf32_rn(__fdividef(x1, 1.f + __expf(-x1)));
                hi.x = tf32_rn(__fdividef(x2, 1.f + __expf(-x2)));
                hi.y = tf32_rn(__fdividef(x3, 1.f + __expf(-x3)));
                int g = c0 >> 2, cm = c0 & 3;
                *(float2*)(smem + SM_BUF + 4 * (rl * 128 + ((g ^ (rl & 7)) << 2) + cm)) = lo;
                *(float2*)(smem + SM_BUF + 4 * (rh * 128 + ((g ^ (rh & 7)) << 2) + cm)) = hi;
            }
        }
    }   // acc dies here
    __syncthreads();       // S2: H complete

    // ======== GEMM2: D2 = H[128,128] @ w2 ; B frags via LDG from fragment image ========
    float acc2[2][8][4];
    #pragma unroll
    for (int mt = 0; mt < 2; mt++)
        #pragma unroll
        for (int nt = 0; nt < 8; nt++)
            #pragma unroll
            for (int q = 0; q < 4; q++) acc2[mt][nt][q] = 0.f;

    const float4* w2f = (const float4*)g_w2frag;
    #pragma unroll
    for (int kp = 0; kp < 8; kp++) {
        uint32_t a[2][2][4];
        #pragma unroll
        for (int mt = 0; mt < 2; mt++)
            #pragma unroll
            for (int ksl = 0; ksl < 2; ksl++) {
                int ks = kp * 2 + ksl;
                int row = wr * 32 + mt * 16 + (lane & 15);
                int g = ks * 2 + (lane >> 4);
                ldsm4(a[mt][ksl][0], a[mt][ksl][1], a[mt][ksl][2], a[mt][ksl][3],
                      sb + SM_BUF + 4 * (row * 128 + ((g ^ (row & 7)) << 2)));
            }
        #pragma unroll
        for (int nt = 0; nt < 8; nt++) {
            float4 bf = w2f[(kp * 16 + wc * 8 + nt) * 32 + lane];
            #pragma unroll
            for (int mt = 0; mt < 2; mt++) {
                mma_tf32(acc2[mt][nt], a[mt][0][0], a[mt][0][1], a[mt][0][2], a[mt][0][3],
                         __float_as_uint(bf.x), __float_as_uint(bf.y));
                mma_tf32(acc2[mt][nt], a[mt][1][0], a[mt][1][1], a[mt][1][2], a[mt][1][3],
                         __float_as_uint(bf.z), __float_as_uint(bf.w));
            }
        }
    }

    // ======== Epilogue 2: +b2, LayerNorm, residual, direct STG ========
    {
        const float* sb2 = (const float*)(smem + SM_B2);
        const int q = lane & 3, rq = lane >> 2;
        float s1[2][2], s2[2][2];
        #pragma unroll
        for (int mt = 0; mt < 2; mt++) { s1[mt][0] = s1[mt][1] = s2[mt][0] = s2[mt][1] = 0.f; }
        #pragma unroll
        for (int mt = 0; mt < 2; mt++)
            #pragma unroll
            for (int nt = 0; nt < 8; nt++) {
                int c0 = wc * 64 + nt * 8 + 2 * q;
                float y0 = acc2[mt][nt][0] + sb2[c0];
                float y1 = acc2[mt][nt][1] + sb2[c0 + 1];
                float y2 = acc2[mt][nt][2] + sb2[c0];
                float y3 = acc2[mt][nt][3] + sb2[c0 + 1];
                acc2[mt][nt][0] = y0; acc2[mt][nt][1] = y1;
                acc2[mt][nt][2] = y2; acc2[mt][nt][3] = y3;
                s1[mt][0] += y0 + y1; s2[mt][0] += y0 * y0 + y1 * y1;
                s1[mt][1] += y2 + y3; s2[mt][1] += y2 * y2 + y3 * y3;
            }
        #pragma unroll
        for (int mt = 0; mt < 2; mt++)
            #pragma unroll
            for (int h = 0; h < 2; h++) {
                s1[mt][h] += __shfl_xor_sync(0xffffffffu, s1[mt][h], 1);
                s1[mt][h] += __shfl_xor_sync(0xffffffffu, s1[mt][h], 2);
                s2[mt][h] += __shfl_xor_sync(0xffffffffu, s2[mt][h], 1);
                s2[mt][h] += __shfl_xor_sync(0xffffffffu, s2[mt][h], 2);
            }
        float* red1 = (float*)(smem + SM_RED);
        float* red2 = red1 + 256;
        if (q == 0) {
            #pragma unroll
            for (int mt = 0; mt < 2; mt++) {
                int rl = wr * 32 + mt * 16 + rq;
                red1[wc * 128 + rl]     = s1[mt][0];
                red2[wc * 128 + rl]     = s2[mt][0];
                red1[wc * 128 + rl + 8] = s1[mt][1];
                red2[wc * 128 + rl + 8] = s2[mt][1];
            }
        }
        __syncthreads();   // S3: red ready
        const float* sg  = (const float*)(smem + SM_GAMMA);
        const float* sbt = (const float*)(smem + SM_BETA);
        #pragma unroll
        for (int mt = 0; mt < 2; mt++)
            #pragma unroll
            for (int h = 0; h < 2; h++) {
                int r = wr * 32 + mt * 16 + rq + h * 8;
                float S1 = red1[r] + red1[128 + r];
                float S2 = red2[r] + red2[128 + r];
                float mu = S1 * (1.f / 128.f);
                float rs = rsqrtf(S2 * (1.f / 128.f) - mu * mu + LN_EPS);
                if (r < valid) {
                    const size_t e = (size_t)(e0 + r);
                    #pragma unroll
                    for (int nt = 0; nt < 8; nt++) {
                        int c0 = wc * 64 + nt * 8 + 2 * q;
                        float2 ef = *(const float2*)(efeat + e * DD + c0);
                        float2 o;
                        o.x = (acc2[mt][nt][2 * h]     - mu) * rs * sg[c0]     + sbt[c0]     + ef.x;
                        o.y = (acc2[mt][nt][2 * h + 1] - mu) * rs * sg[c0 + 1] + sbt[c0 + 1] + ef.y;
                        *(float2*)(out + e * DD + c0) = o;
                    }
                }
            }
    }
}

extern "C" void kernel_launch(void* const* d_in, const int* in_sizes, int n_in,
                              void* d_out, int out_size) {
    const float* efeat = (const float*)d_in[0];
    const float* nfeat = (const float*)d_in[1];
    const void*  src   = d_in[2];
    const void*  dst   = d_in[3];
    const float* w1    = (const float*)d_in[4];
    const float* b1    = (const float*)d_in[5];
    const float* w2    = (const float*)d_in[6];
    const float* b2    = (const float*)d_in[7];
    const float* gamma = (const float*)d_in[8];
    const float* beta  = (const float*)d_in[9];
    float* out = (float*)d_out;

    cudaFuncSetAttribute(fused_mma_kernel,
                         cudaFuncAttributeMaxDynamicSharedMemorySize, SMEM_TOTAL);

    prep_weights_kernel<<<448, 256>>>(w1, w2, src);
    const long long need = (long long)EN * DD + (long long)NN * DD;
    if ((long long)out_size >= need) {
        int n4 = NN * DD / 4;
        copy_nfeat_kernel<<<(n4 + 255) / 256, 256>>>(
            (const float4*)nfeat, (float4*)(out + (size_t)EN * DD), n4);
    }
    fused_mma_kernel<<<NCTAS, THREADS, SMEM_TOTAL>>>(
        efeat, nfeat, src, dst, b1, b2, gamma, beta, out);
}

// round 13
// speedup vs baseline: 1.2889x; 1.0184x over previous
#include <cuda_runtime.h>
#include <cuda_fp16.h>
#include <cstdint>

#define EN 500000
#define NN 100000
#define DD 128
#define LN_EPS 1e-5f
#define TILE_M 128
#define NCTAS 3907
#define THREADS 256

// SMEM map (bytes into dynamic smem)
#define SM_B1    0
#define SM_B2    512
#define SM_GAMMA 1024
#define SM_BETA  1536
#define SM_SRC   2048
#define SM_DST   2560
#define SM_BUF   4096        // A0 (32KB fp32), A1 (32KB) ; H (fp16, 32KB) overlays A0
#define SM_BB    69632       // B0, B1 (16KB fp16 each)
#define SM_RED   102400      // 2KB reductions
#define SMEM_TOTAL 104448

__device__ int g_idx64;
__device__ __half g_w1h[6 * 8192];    // fp16 w1 chunk images: [chunk][n=128][k=64 swizzled]
__device__ __half g_w2f[128 * 128];   // fp16 fragment-ordered w2: uint2 per (ku*16+nt, lane)

// ---------------- helpers ----------------
__device__ __forceinline__ uint32_t smem_u32(const void* p) {
    uint32_t a;
    asm("{ .reg .u64 t; cvta.to.shared.u64 t, %1; cvt.u32.u64 %0, t; }" : "=r"(a) : "l"(p));
    return a;
}
__device__ __forceinline__ uint32_t pack_h2(float x, float y) {
    __half2 h = __floats2half2_rn(x, y);
    return *(uint32_t*)&h;
}
__device__ __forceinline__ void cp16(uint32_t dst, const void* src) {
    asm volatile("cp.async.cg.shared.global [%0], [%1], 16;"
        :: "r"(dst), "l"(__cvta_generic_to_global(src)));
}
__device__ __forceinline__ void cp_commit() { asm volatile("cp.async.commit_group;"); }
__device__ __forceinline__ void cp_wait0()  { asm volatile("cp.async.wait_group 0;"); }

__device__ __forceinline__ void ldsm4(uint32_t& d0, uint32_t& d1, uint32_t& d2, uint32_t& d3,
                                      uint32_t addr) {
    asm volatile("ldmatrix.sync.aligned.m8n8.x4.shared.b16 {%0,%1,%2,%3}, [%4];"
        : "=r"(d0), "=r"(d1), "=r"(d2), "=r"(d3) : "r"(addr));
}
__device__ __forceinline__ void mma_f16(float* c, uint32_t a0, uint32_t a1, uint32_t a2,
                                        uint32_t a3, uint32_t b0, uint32_t b1) {
    asm volatile("mma.sync.aligned.m16n8k16.row.col.f32.f16.f16.f32 "
        "{%0,%1,%2,%3},{%4,%5,%6,%7},{%8,%9},{%0,%1,%2,%3};"
        : "+f"(c[0]), "+f"(c[1]), "+f"(c[2]), "+f"(c[3])
        : "r"(a0), "r"(a1), "r"(a2), "r"(a3), "r"(b0), "r"(b1));
}

// ---------------- prep kernel (detect + fp16 weight images) ----------------
__global__ void prep_weights_kernel(const float* __restrict__ w1,
                                    const float* __restrict__ w2,
                                    const void* __restrict__ src) {
    int i = blockIdx.x * blockDim.x + threadIdx.x;   // 0..65535
    if (i == 0) {
        const long long* p = (const long long*)src;
        int ok = 1;
        #pragma unroll
        for (int t = 0; t < 32; t++) {
            long long v = p[t];
            if (v < 0 || v >= (long long)NN) ok = 0;
        }
        g_idx64 = ok;
    }
    if (i < 49152) {
        // w1 chunk image: n-major rows of 64 halves (128B), 16B-granule swizzle
        int chunk = i >> 13, idx = i & 8191;
        int n = idx >> 6, k = idx & 63;
        float v = w1[(size_t)(chunk * 64 + k) * 128 + n];
        g_w1h[chunk * 8192 + n * 64 + (((k >> 3) ^ (n & 7)) << 3) + (k & 7)] =
            __float2half_rn(v);
    } else if (i < 65536) {
        // w2 fragment image: per (s = ku*16+nt, lane), regs r0,r1; halves h0,h1
        int t = i - 49152;                 // 0..16383
        int h = t & 1, r = (t >> 1) & 1, lane = (t >> 2) & 31, s = t >> 7;
        int nt = s & 15, ku = s >> 4;
        int k = ku * 16 + (lane & 3) * 2 + h + r * 8;
        int n = nt * 8 + (lane >> 2);
        g_w2f[s * 128 + lane * 4 + r * 2 + h] = __float2half_rn(w2[(size_t)k * 128 + n]);
    }
}

__global__ void copy_nfeat_kernel(const float4* __restrict__ in,
                                  float4* __restrict__ out, int n4) {
    int i = blockIdx.x * blockDim.x + threadIdx.x;
    if (i < n4) out[i] = in[i];
}

// ---------------- main fused kernel ----------------
__global__ __launch_bounds__(THREADS, 2) void fused_mma_kernel(
    const float* __restrict__ efeat, const float* __restrict__ nfeat,
    const void* __restrict__ src_raw, const void* __restrict__ dst_raw,
    const float* __restrict__ b1, const float* __restrict__ b2,
    const float* __restrict__ gamma, const float* __restrict__ beta,
    float* __restrict__ out)
{
    extern __shared__ __align__(1024) char smem[];
    const uint32_t sb = smem_u32(smem);
    const int tid = threadIdx.x;
    const int wid = tid >> 5, lane = tid & 31;
    const int wr = wid & 3, wc = wid >> 2;
    const int e0 = blockIdx.x * TILE_M;
    const int valid = min(TILE_M, EN - e0);

    if (tid < 128) {
        ((float*)(smem + SM_B1))[tid]    = b1[tid];
        ((float*)(smem + SM_B2))[tid]    = b2[tid];
        ((float*)(smem + SM_GAMMA))[tid] = gamma[tid];
        ((float*)(smem + SM_BETA))[tid]  = beta[tid];
        int e = min(e0 + tid, EN - 1);
        int s, d;
        if (g_idx64) {
            s = (int)((const long long*)src_raw)[e];
            d = (int)((const long long*)dst_raw)[e];
        } else {
            s = ((const int*)src_raw)[e];
            d = ((const int*)dst_raw)[e];
        }
        ((int*)(smem + SM_SRC))[tid] = s;
        ((int*)(smem + SM_DST))[tid] = d;
    }
    __syncthreads();

    const int* ssrc = (const int*)(smem + SM_SRC);
    const int* sdst = (const int*)(smem + SM_DST);

    // A chunk (fp32, K=64): thread t -> row t>>1, col-half t&1
    auto cpA = [&](int kc, int Aoff) {
        const int rr = tid >> 1, ch = tid & 1;
        const float* rp;
        if (kc < 2)      rp = efeat + (size_t)min(e0 + rr, EN - 1) * DD;
        else if (kc < 4) rp = nfeat + (size_t)ssrc[rr] * DD;
        else             rp = nfeat + (size_t)sdst[rr] * DD;
        rp += (kc & 1) * 64 + ch * 32;
        const uint32_t dst = sb + Aoff + rr * 256;
        #pragma unroll
        for (int j = 0; j < 8; j++) {
            int gk = ch * 8 + j;
            cp16(dst + ((gk ^ (rr & 7)) << 4), rp + j * 4);
        }
    };
    auto cpB = [&](int kc, int Boff) {
        const char* srcp = (const char*)g_w1h + kc * 16384;
        #pragma unroll
        for (int t = 0; t < 4; t++) {
            int i = tid + t * 256;
            cp16(sb + Boff + i * 16, srcp + i * 16);
        }
    };
    // A fragment half2: fp32 smem -> LDS.64 -> cvt RN
    auto ldsA2 = [&](int Aoff, int row, int k) -> uint32_t {
        const float2 f = *(const float2*)(smem + Aoff + row * 256
                          + (((k >> 2) ^ (row & 7)) << 4) + (k & 3) * 4);
        return pack_h2(f.x, f.y);
    };

    const int q = lane & 3, rq = lane >> 2;

    // ======== GEMM1: K=384 in 6 chunks of 64, fp16 mma, double buffered ========
    {
        float acc[2][8][4];
        #pragma unroll
        for (int mt = 0; mt < 2; mt++)
            #pragma unroll
            for (int nt = 0; nt < 8; nt++)
                #pragma unroll
                for (int j = 0; j < 4; j++) acc[mt][nt][j] = 0.f;

        cpA(0, SM_BUF); cpB(0, SM_BB); cp_commit();
        for (int kc = 0; kc < 6; kc++) {
            const int s = kc & 1;
            cp_wait0();
            __syncthreads();
            if (kc + 1 < 6) {
                cpA(kc + 1, SM_BUF + (1 - s) * 32768);
                cpB(kc + 1, SM_BB + (1 - s) * 16384);
                cp_commit();
            }
            const int Aoff = SM_BUF + s * 32768;
            const uint32_t Bsh = sb + SM_BB + s * 16384;
            #pragma unroll
            for (int ku = 0; ku < 4; ku++) {
                uint32_t a[2][4];
                #pragma unroll
                for (int mt = 0; mt < 2; mt++) {
                    int r0 = wr * 32 + mt * 16 + rq;
                    int k0 = ku * 16 + q * 2;
                    a[mt][0] = ldsA2(Aoff, r0,     k0);
                    a[mt][1] = ldsA2(Aoff, r0 + 8, k0);
                    a[mt][2] = ldsA2(Aoff, r0,     k0 + 8);
                    a[mt][3] = ldsA2(Aoff, r0 + 8, k0 + 8);
                }
                #pragma unroll
                for (int ntp = 0; ntp < 4; ntp++) {
                    int nn = wc * 64 + ntp * 16 + ((lane >> 4) << 3) + (lane & 7);
                    int gk = ku * 2 + ((lane >> 3) & 1);
                    uint32_t b0, b1r, b2r, b3;
                    ldsm4(b0, b1r, b2r, b3, Bsh + nn * 128 + ((gk ^ (nn & 7)) << 4));
                    #pragma unroll
                    for (int mt = 0; mt < 2; mt++) {
                        mma_f16(acc[mt][ntp * 2],     a[mt][0], a[mt][1], a[mt][2], a[mt][3], b0,  b1r);
                        mma_f16(acc[mt][ntp * 2 + 1], a[mt][0], a[mt][1], a[mt][2], a[mt][3], b2r, b3);
                    }
                }
            }
        }
        // last chunk used A1/B1; H (fp16, 32KB) overlays A0 only — no bar needed here.

        // ======== Epilogue 1: +b1, SiLU, fp16 -> H ========
        const float* sb1 = (const float*)(smem + SM_B1);
        #pragma unroll
        for (int mt = 0; mt < 2; mt++) {
            int rl = wr * 32 + mt * 16 + rq, rh = rl + 8;
            #pragma unroll
            for (int nt = 0; nt < 8; nt++) {
                int c0 = wc * 64 + nt * 8 + 2 * q;
                float x0 = acc[mt][nt][0] + sb1[c0];
                float x1 = acc[mt][nt][1] + sb1[c0 + 1];
                float x2 = acc[mt][nt][2] + sb1[c0];
                float x3 = acc[mt][nt][3] + sb1[c0 + 1];
                float s0 = __fdividef(x0, 1.f + __expf(-x0));
                float s1 = __fdividef(x1, 1.f + __expf(-x1));
                float s2 = __fdividef(x2, 1.f + __expf(-x2));
                float s3 = __fdividef(x3, 1.f + __expf(-x3));
                int go = (((c0 >> 3) ^ (rl & 7)) << 4) + (c0 & 7) * 2;
                int gh = (((c0 >> 3) ^ (rh & 7)) << 4) + (c0 & 7) * 2;
                *(uint32_t*)(smem + SM_BUF + rl * 256 + go) = pack_h2(s0, s1);
                *(uint32_t*)(smem + SM_BUF + rh * 256 + gh) = pack_h2(s2, s3);
            }
        }
    }   // acc dies
    __syncthreads();       // H complete (cross-warp: wc pair writes both col halves)

    // ======== GEMM2: D2 = H[128,128] @ w2 (fp16), B frags via uint2 LDG ========
    float acc2[2][8][4];
    #pragma unroll
    for (int mt = 0; mt < 2; mt++)
        #pragma unroll
        for (int nt = 0; nt < 8; nt++)
            #pragma unroll
            for (int j = 0; j < 4; j++) acc2[mt][nt][j] = 0.f;

    const uint2* w2f2 = (const uint2*)g_w2f;
    #pragma unroll
    for (int ku = 0; ku < 8; ku++) {
        uint2 bf[8];
        #pragma unroll
        for (int nt = 0; nt < 8; nt++)
            bf[nt] = w2f2[(ku * 16 + wc * 8 + nt) * 32 + lane];
        uint32_t a[2][4];
        #pragma unroll
        for (int mt = 0; mt < 2; mt++) {
            int row = wr * 32 + mt * 16 + (lane & 15);
            int gk = ku * 2 + (lane >> 4);
            ldsm4(a[mt][0], a[mt][1], a[mt][2], a[mt][3],
                  sb + SM_BUF + row * 256 + ((gk ^ (row & 7)) << 4));
        }
        #pragma unroll
        for (int nt = 0; nt < 8; nt++)
            #pragma unroll
            for (int mt = 0; mt < 2; mt++)
                mma_f16(acc2[mt][nt], a[mt][0], a[mt][1], a[mt][2], a[mt][3],
                        bf[nt].x, bf[nt].y);
    }

    // ======== Epilogue 2: +b2, LayerNorm, residual, direct STG ========
    {
        const float* sb2 = (const float*)(smem + SM_B2);
        float s1[2][2], s2[2][2];
        #pragma unroll
        for (int mt = 0; mt < 2; mt++) { s1[mt][0] = s1[mt][1] = s2[mt][0] = s2[mt][1] = 0.f; }
        #pragma unroll
        for (int mt = 0; mt < 2; mt++)
            #pragma unroll
            for (int nt = 0; nt < 8; nt++) {
                int c0 = wc * 64 + nt * 8 + 2 * q;
                float y0 = acc2[mt][nt][0] + sb2[c0];
                float y1 = acc2[mt][nt][1] + sb2[c0 + 1];
                float y2 = acc2[mt][nt][2] + sb2[c0];
                float y3 = acc2[mt][nt][3] + sb2[c0 + 1];
                acc2[mt][nt][0] = y0; acc2[mt][nt][1] = y1;
                acc2[mt][nt][2] = y2; acc2[mt][nt][3] = y3;
                s1[mt][0] += y0 + y1; s2[mt][0] += y0 * y0 + y1 * y1;
                s1[mt][1] += y2 + y3; s2[mt][1] += y2 * y2 + y3 * y3;
            }
        #pragma unroll
        for (int mt = 0; mt < 2; mt++)
            #pragma unroll
            for (int h = 0; h < 2; h++) {
                s1[mt][h] += __shfl_xor_sync(0xffffffffu, s1[mt][h], 1);
                s1[mt][h] += __shfl_xor_sync(0xffffffffu, s1[mt][h], 2);
                s2[mt][h] += __shfl_xor_sync(0xffffffffu, s2[mt][h], 1);
                s2[mt][h] += __shfl_xor_sync(0xffffffffu, s2[mt][h], 2);
            }
        float* red1 = (float*)(smem + SM_RED);
        float* red2 = red1 + 256;
        if (q == 0) {
            #pragma unroll
            for (int mt = 0; mt < 2; mt++) {
                int rl = wr * 32 + mt * 16 + rq;
                red1[wc * 128 + rl]     = s1[mt][0];
                red2[wc * 128 + rl]     = s2[mt][0];
                red1[wc * 128 + rl + 8] = s1[mt][1];
                red2[wc * 128 + rl + 8] = s2[mt][1];
            }
        }
        __syncthreads();
        const float* sg  = (const float*)(smem + SM_GAMMA);
        const float* sbt = (const float*)(smem + SM_BETA);
        #pragma unroll
        for (int mt = 0; mt < 2; mt++)
            #pragma unroll
            for (int h = 0; h < 2; h++) {
                int r = wr * 32 + mt * 16 + rq + h * 8;
                float S1 = red1[r] + red1[128 + r];
                float S2 = red2[r] + red2[128 + r];
                float mu = S1 * (1.f / 128.f);
                float rs = rsqrtf(S2 * (1.f / 128.f) - mu * mu + LN_EPS);
                if (r < valid) {
                    const size_t e = (size_t)(e0 + r);
                    #pragma unroll
                    for (int nt = 0; nt < 8; nt++) {
                        int c0 = wc * 64 + nt * 8 + 2 * q;
                        float2 ef = *(const float2*)(efeat + e * DD + c0);
                        float2 o;
                        o.x = (acc2[mt][nt][2 * h]     - mu) * rs * sg[c0]     + sbt[c0]     + ef.x;
                        o.y = (acc2[mt][nt][2 * h + 1] - mu) * rs * sg[c0 + 1] + sbt[c0 + 1] + ef.y;
                        *(float2*)(out + e * DD + c0) = o;
                    }
                }
            }
    }
}

extern "C" void kernel_launch(void* const* d_in, const int* in_sizes, int n_in,
                              void* d_out, int out_size) {
    const float* efeat = (const float*)d_in[0];
    const float* nfeat = (const float*)d_in[1];
    const void*  src   = d_in[2];
    const void*  dst   = d_in[3];
    const float* w1    = (const float*)d_in[4];
    const float* b1    = (const float*)d_in[5];
    const float* w2    = (const float*)d_in[6];
    const float* b2    = (const float*)d_in[7];
    const float* gamma = (const float*)d_in[8];
    const float* beta  = (const float*)d_in[9];
    float* out = (float*)d_out;

    cudaFuncSetAttribute(fused_mma_kernel,
                         cudaFuncAttributeMaxDynamicSharedMemorySize, SMEM_TOTAL);

    prep_weights_kernel<<<256, 256>>>(w1, w2, src);
    const long long need = (long long)EN * DD + (long long)NN * DD;
    if ((long long)out_size >= need) {
        int n4 = NN * DD / 4;
        copy_nfeat_kernel<<<(n4 + 255) / 256, 256>>>(
            (const float4*)nfeat, (float4*)(out + (size_t)EN * DD), n4);
    }
    fused_mma_kernel<<<NCTAS, THREADS, SMEM_TOTAL>>>(
        efeat, nfeat, src, dst, b1, b2, gamma, beta, out);
}

// round 16
// speedup vs baseline: 1.3164x; 1.0214x over previous
#include <cuda_runtime.h>
#include <cuda_fp16.h>
#include <cstdint>

#define EN 500000
#define NN 100000
#define NPAD 100096
#define DD 128
#define LN_EPS 1e-5f
#define TILE_M 128
#define NCTAS 3907
#define THREADS 256

// SMEM map (bytes into dynamic smem)
#define SM_B1    0
#define SM_B2    512
#define SM_GAMMA 1024
#define SM_BETA  1536
#define SM_SRC   2048
#define SM_DST   2560
#define SM_BUF   4096        // A0 (32KB fp32), A1 (32KB) ; H (fp16, 32KB) overlays A0
#define SM_BB    69632       // B0, B1 (16KB fp16 each)
#define SM_RED   102400      // 2KB reductions
#define SMEM_TOTAL 104448

__device__ int g_idx64;
__device__ __half g_w1h[6 * 8192];    // fp16 w1 chunk images: [chunk][n=128][k=64 swizzled]
__device__ __half g_w2f[128 * 128];   // fp16 fragment-ordered w2
__device__ float g_PQ[2ll * NPAD * 128];  // node projections: P (src block), Q (dst block)

// ---------------- helpers ----------------
__device__ __forceinline__ uint32_t smem_u32(const void* p) {
    uint32_t a;
    asm("{ .reg .u64 t; cvta.to.shared.u64 t, %1; cvt.u32.u64 %0, t; }" : "=r"(a) : "l"(p));
    return a;
}
__device__ __forceinline__ uint32_t pack_h2(float x, float y) {
    __half2 h = __floats2half2_rn(x, y);
    return *(uint32_t*)&h;
}
__device__ __forceinline__ void cp16(uint32_t dst, const void* src) {
    asm volatile("cp.async.cg.shared.global [%0], [%1], 16;"
        :: "r"(dst), "l"(__cvta_generic_to_global(src)));
}
__device__ __forceinline__ void cp_commit() { asm volatile("cp.async.commit_group;"); }
__device__ __forceinline__ void cp_wait0()  { asm volatile("cp.async.wait_group 0;"); }
__device__ __forceinline__ void cp_wait1()  { asm volatile("cp.async.wait_group 1;"); }

__device__ __forceinline__ void ldsm4(uint32_t& d0, uint32_t& d1, uint32_t& d2, uint32_t& d3,
                                      uint32_t addr) {
    asm volatile("ldmatrix.sync.aligned.m8n8.x4.shared.b16 {%0,%1,%2,%3}, [%4];"
        : "=r"(d0), "=r"(d1), "=r"(d2), "=r"(d3) : "r"(addr));
}
__device__ __forceinline__ void mma_f16(float* c, uint32_t a0, uint32_t a1, uint32_t a2,
                                        uint32_t a3, uint32_t b0, uint32_t b1) {
    asm volatile("mma.sync.aligned.m16n8k16.row.col.f32.f16.f16.f32 "
        "{%0,%1,%2,%3},{%4,%5,%6,%7},{%8,%9},{%0,%1,%2,%3};"
        : "+f"(c[0]), "+f"(c[1]), "+f"(c[2]), "+f"(c[3])
        : "r"(a0), "r"(a1), "r"(a2), "r"(a3), "r"(b0), "r"(b1));
}

// ---------------- prep kernel (detect + fp16 weight images) ----------------
__global__ void prep_weights_kernel(const float* __restrict__ w1,
                                    const float* __restrict__ w2,
                                    const void* __restrict__ src) {
    int i = blockIdx.x * blockDim.x + threadIdx.x;   // 0..65535
    if (i == 0) {
        const long long* p = (const long long*)src;
        int ok = 1;
        #pragma unroll
        for (int t = 0; t < 32; t++) {
            long long v = p[t];
            if (v < 0 || v >= (long long)NN) ok = 0;
        }
        g_idx64 = ok;
    }
    if (i < 49152) {
        int chunk = i >> 13, idx = i & 8191;
        int n = idx >> 6, k = idx & 63;
        float v = w1[(size_t)(chunk * 64 + k) * 128 + n];
        g_w1h[chunk * 8192 + n * 64 + (((k >> 3) ^ (n & 7)) << 3) + (k & 7)] =
            __float2half_rn(v);
    } else if (i < 65536) {
        int t = i - 49152;
        int h = t & 1, r = (t >> 1) & 1, lane = (t >> 2) & 31, s = t >> 7;
        int nt = s & 15, ku = s >> 4;
        int k = ku * 16 + (lane & 3) * 2 + h + r * 8;
        int n = nt * 8 + (lane >> 2);
        g_w2f[s * 128 + lane * 4 + r * 2 + h] = __float2half_rn(w2[(size_t)k * 128 + n]);
    }
}

__global__ void copy_nfeat_kernel(const float4* __restrict__ in,
                                  float4* __restrict__ out, int n4) {
    int i = blockIdx.x * blockDim.x + threadIdx.x;
    if (i < n4) out[i] = in[i];
}

// ---------------- node projection: P = nfeat@w1b, Q = nfeat@w1c ----------------
__global__ __launch_bounds__(THREADS, 2) void node_proj_kernel(
    const float* __restrict__ nfeat)
{
    extern __shared__ __align__(1024) char smem[];
    const uint32_t sb = smem_u32(smem);
    const int tid = threadIdx.x;
    const int lane = tid & 31;
    const int wr = (tid >> 5) & 3, wc = tid >> 7;
    const int which = blockIdx.y;            // 0 = P (w1b), 1 = Q (w1c)
    const int n0 = blockIdx.x * TILE_M;
    const int q = lane & 3, rq = lane >> 2;

    // prefetch both K-chunks
    {
        const int rr = tid >> 1, ch = tid & 1;
        #pragma unroll
        for (int kc = 0; kc < 2; kc++) {
            const float* rp = nfeat + (size_t)min(n0 + rr, NN - 1) * DD + kc * 64 + ch * 32;
            const uint32_t dst = sb + SM_BUF + kc * 32768 + rr * 256;
            #pragma unroll
            for (int j = 0; j < 8; j++) {
                int gk = ch * 8 + j;
                cp16(dst + ((gk ^ (rr & 7)) << 4), rp + j * 4);
            }
            const char* srcp = (const char*)g_w1h + (2 + 2 * which + kc) * 16384;
            #pragma unroll
            for (int t = 0; t < 4; t++) {
                int i = tid + t * 256;
                cp16(sb + SM_BB + kc * 16384 + i * 16, srcp + i * 16);
            }
            cp_commit();
        }
    }

    float acc[2][8][4];
    #pragma unroll
    for (int mt = 0; mt < 2; mt++)
        #pragma unroll
        for (int nt = 0; nt < 8; nt++)
            #pragma unroll
            for (int j = 0; j < 4; j++) acc[mt][nt][j] = 0.f;

    #pragma unroll
    for (int kc = 0; kc < 2; kc++) {
        if (kc == 0) cp_wait1(); else cp_wait0();
        __syncthreads();
        const int Aoff = SM_BUF + kc * 32768;
        const uint32_t Bsh = sb + SM_BB + kc * 16384;
        #pragma unroll
        for (int ku = 0; ku < 4; ku++) {
            uint32_t a[2][4];
            #pragma unroll
            for (int mt = 0; mt < 2; mt++) {
                int r0 = wr * 32 + mt * 16 + rq;
                int k0 = ku * 16 + q * 2;
                const float2 f0 = *(const float2*)(smem + Aoff + r0 * 256 + (((k0 >> 2) ^ (r0 & 7)) << 4) + (k0 & 3) * 4);
                const float2 f1 = *(const float2*)(smem + Aoff + (r0 + 8) * 256 + (((k0 >> 2) ^ ((r0 + 8) & 7)) << 4) + (k0 & 3) * 4);
                int k8 = k0 + 8;
                const float2 f2 = *(const float2*)(smem + Aoff + r0 * 256 + (((k8 >> 2) ^ (r0 & 7)) << 4) + (k8 & 3) * 4);
                const float2 f3 = *(const float2*)(smem + Aoff + (r0 + 8) * 256 + (((k8 >> 2) ^ ((r0 + 8) & 7)) << 4) + (k8 & 3) * 4);
                a[mt][0] = pack_h2(f0.x, f0.y); a[mt][1] = pack_h2(f1.x, f1.y);
                a[mt][2] = pack_h2(f2.x, f2.y); a[mt][3] = pack_h2(f3.x, f3.y);
            }
            #pragma unroll
            for (int ntp = 0; ntp < 4; ntp++) {
                int nn = wc * 64 + ntp * 16 + ((lane >> 4) << 3) + (lane & 7);
                int gk = ku * 2 + ((lane >> 3) & 1);
                uint32_t b0, b1r, b2r, b3;
                ldsm4(b0, b1r, b2r, b3, Bsh + nn * 128 + ((gk ^ (nn & 7)) << 4));
                #pragma unroll
                for (int mt = 0; mt < 2; mt++) {
                    mma_f16(acc[mt][ntp * 2],     a[mt][0], a[mt][1], a[mt][2], a[mt][3], b0,  b1r);
                    mma_f16(acc[mt][ntp * 2 + 1], a[mt][0], a[mt][1], a[mt][2], a[mt][3], b2r, b3);
                }
            }
        }
    }

    // store projections fp32
    float* dst = g_PQ + (size_t)which * NPAD * 128;
    #pragma unroll
    for (int mt = 0; mt < 2; mt++) {
        int rl = wr * 32 + mt * 16 + rq, rh = rl + 8;
        int nl = n0 + rl, nh = n0 + rh;
        #pragma unroll
        for (int nt = 0; nt < 8; nt++) {
            int c0 = wc * 64 + nt * 8 + 2 * q;
            if (nl < NN) *(float2*)(dst + (size_t)nl * 128 + c0) =
                make_float2(acc[mt][nt][0], acc[mt][nt][1]);
            if (nh < NN) *(float2*)(dst + (size_t)nh * 128 + c0) =
                make_float2(acc[mt][nt][2], acc[mt][nt][3]);
        }
    }
}

// ---------------- main fused edge kernel ----------------
__global__ __launch_bounds__(THREADS, 2) void fused_mma_kernel(
    const float* __restrict__ efeat, const float* __restrict__ nfeat,
    const void* __restrict__ src_raw, const void* __restrict__ dst_raw,
    const float* __restrict__ b1, const float* __restrict__ b2,
    const float* __restrict__ gamma, const float* __restrict__ beta,
    float* __restrict__ out)
{
    extern __shared__ __align__(1024) char smem[];
    const uint32_t sb = smem_u32(smem);
    const int tid = threadIdx.x;
    const int wid = tid >> 5, lane = tid & 31;
    const int wr = wid & 3, wc = wid >> 2;
    const int e0 = blockIdx.x * TILE_M;
    const int valid = min(TILE_M, EN - e0);
    const int q = lane & 3, rq = lane >> 2;

    // prefetch both efeat K-chunks immediately (no gather dependency)
    {
        const int rr = tid >> 1, ch = tid & 1;
        #pragma unroll
        for (int kc = 0; kc < 2; kc++) {
            const float* rp = efeat + (size_t)min(e0 + rr, EN - 1) * DD + kc * 64 + ch * 32;
            const uint32_t dst = sb + SM_BUF + kc * 32768 + rr * 256;
            #pragma unroll
            for (int j = 0; j < 8; j++) {
                int gk = ch * 8 + j;
                cp16(dst + ((gk ^ (rr & 7)) << 4), rp + j * 4);
            }
            const char* srcp = (const char*)g_w1h + kc * 16384;
            #pragma unroll
            for (int t = 0; t < 4; t++) {
                int i = tid + t * 256;
                cp16(sb + SM_BB + kc * 16384 + i * 16, srcp + i * 16);
            }
            cp_commit();
        }
    }

    if (tid < 128) {
        ((float*)(smem + SM_B1))[tid]    = b1[tid];
        ((float*)(smem + SM_B2))[tid]    = b2[tid];
        ((float*)(smem + SM_GAMMA))[tid] = gamma[tid];
        ((float*)(smem + SM_BETA))[tid]  = beta[tid];
        int e = min(e0 + tid, EN - 1);
        int s, d;
        if (g_idx64) {
            s = (int)((const long long*)src_raw)[e];
            d = (int)((const long long*)dst_raw)[e];
        } else {
            s = ((const int*)src_raw)[e];
            d = ((const int*)dst_raw)[e];
        }
        ((int*)(smem + SM_SRC))[tid] = s;
        ((int*)(smem + SM_DST))[tid] = d;
    }

    const int* ssrc = (const int*)(smem + SM_SRC);
    const int* sdst = (const int*)(smem + SM_DST);

    // ======== GEMM1': efeat[128,128] @ w1a, 2 chunks ========
    {
        float acc[2][8][4];
        #pragma unroll
        for (int mt = 0; mt < 2; mt++)
            #pragma unroll
            for (int nt = 0; nt < 8; nt++)
                #pragma unroll
                for (int j = 0; j < 4; j++) acc[mt][nt][j] = 0.f;

        #pragma unroll
        for (int kc = 0; kc < 2; kc++) {
            if (kc == 0) cp_wait1(); else cp_wait0();
            __syncthreads();            // also publishes SM_SRC/SM_DST after kc==0
            const int Aoff = SM_BUF + kc * 32768;
            const uint32_t Bsh = sb + SM_BB + kc * 16384;
            #pragma unroll
            for (int ku = 0; ku < 4; ku++) {
                uint32_t a[2][4];
                #pragma unroll
                for (int mt = 0; mt < 2; mt++) {
                    int r0 = wr * 32 + mt * 16 + rq;
                    int k0 = ku * 16 + q * 2;
                    const float2 f0 = *(const float2*)(smem + Aoff + r0 * 256 + (((k0 >> 2) ^ (r0 & 7)) << 4) + (k0 & 3) * 4);
                    const float2 f1 = *(const float2*)(smem + Aoff + (r0 + 8) * 256 + (((k0 >> 2) ^ ((r0 + 8) & 7)) << 4) + (k0 & 3) * 4);
                    int k8 = k0 + 8;
                    const float2 f2 = *(const float2*)(smem + Aoff + r0 * 256 + (((k8 >> 2) ^ (r0 & 7)) << 4) + (k8 & 3) * 4);
                    const float2 f3 = *(const float2*)(smem + Aoff + (r0 + 8) * 256 + (((k8 >> 2) ^ ((r0 + 8) & 7)) << 4) + (k8 & 3) * 4);
                    a[mt][0] = pack_h2(f0.x, f0.y); a[mt][1] = pack_h2(f1.x, f1.y);
                    a[mt][2] = pack_h2(f2.x, f2.y); a[mt][3] = pack_h2(f3.x, f3.y);
                }
                #pragma unroll
                for (int ntp = 0; ntp < 4; ntp++) {
                    int nn = wc * 64 + ntp * 16 + ((lane >> 4) << 3) + (lane & 7);
                    int gk = ku * 2 + ((lane >> 3) & 1);
                    uint32_t b0, b1r, b2r, b3;
                    ldsm4(b0, b1r, b2r, b3, Bsh + nn * 128 + ((gk ^ (nn & 7)) << 4));
                    #pragma unroll
                    for (int mt = 0; mt < 2; mt++) {
                        mma_f16(acc[mt][ntp * 2],     a[mt][0], a[mt][1], a[mt][2], a[mt][3], b0,  b1r);
                        mma_f16(acc[mt][ntp * 2 + 1], a[mt][0], a[mt][1], a[mt][2], a[mt][3], b2r, b3);
                    }
                }
            }
        }

        // ======== gather-add node projections: acc += P[src] + Q[dst] ========
        const float* P = g_PQ;
        const float* Q = g_PQ + (size_t)NPAD * 128;
        #pragma unroll
        for (int mt = 0; mt < 2; mt++) {
            int rl = wr * 32 + mt * 16 + rq, rh = rl + 8;
            const float* ps0 = P + (size_t)ssrc[rl] * 128;
            const float* pd0 = Q + (size_t)sdst[rl] * 128;
            const float* ps1 = P + (size_t)ssrc[rh] * 128;
            const float* pd1 = Q + (size_t)sdst[rh] * 128;
            #pragma unroll
            for (int nt = 0; nt < 8; nt++) {
                int c0 = wc * 64 + nt * 8 + 2 * q;
                float2 a0 = *(const float2*)(ps0 + c0);
                float2 b0 = *(const float2*)(pd0 + c0);
                float2 a1 = *(const float2*)(ps1 + c0);
                float2 b1v = *(const float2*)(pd1 + c0);
                acc[mt][nt][0] += a0.x + b0.x;
                acc[mt][nt][1] += a0.y + b0.y;
                acc[mt][nt][2] += a1.x + b1v.x;
                acc[mt][nt][3] += a1.y + b1v.y;
            }
        }

        // ======== Epilogue 1: +b1, SiLU, fp16 -> H (overlays A0) ========
        const float* sb1 = (const float*)(smem + SM_B1);
        #pragma unroll
        for (int mt = 0; mt < 2; mt++) {
            int rl = wr * 32 + mt * 16 + rq, rh = rl + 8;
            #pragma unroll
            for (int nt = 0; nt < 8; nt++) {
                int c0 = wc * 64 + nt * 8 + 2 * q;
                float x0 = acc[mt][nt][0] + sb1[c0];
                float x1 = acc[mt][nt][1] + sb1[c0 + 1];
                float x2 = acc[mt][nt][2] + sb1[c0];
                float x3 = acc[mt][nt][3] + sb1[c0 + 1];
                float s0 = __fdividef(x0, 1.f + __expf(-x0));
                float s1 = __fdividef(x1, 1.f + __expf(-x1));
                float s2 = __fdividef(x2, 1.f + __expf(-x2));
                float s3 = __fdividef(x3, 1.f + __expf(-x3));
                int go = (((c0 >> 3) ^ (rl & 7)) << 4) + (c0 & 7) * 2;
                int gh = (((c0 >> 3) ^ (rh & 7)) << 4) + (c0 & 7) * 2;
                *(uint32_t*)(smem + SM_BUF + rl * 256 + go) = pack_h2(s0, s1);
                *(uint32_t*)(smem + SM_BUF + rh * 256 + gh) = pack_h2(s2, s3);
            }
        }
    }
    __syncthreads();       // H complete

    // ======== GEMM2: D2 = H[128,128] @ w2 (fp16), B frags via uint2 LDG ========
    float acc2[2][8][4];
    #pragma unroll
    for (int mt = 0; mt < 2; mt++)
        #pragma unroll
        for (int nt = 0; nt < 8; nt++)
            #pragma unroll
            for (int j = 0; j < 4; j++) acc2[mt][nt][j] = 0.f;

    const uint2* w2f2 = (const uint2*)g_w2f;
    #pragma unroll
    for (int ku = 0; ku < 8; ku++) {
        uint2 bf[8];
        #pragma unroll
        for (int nt = 0; nt < 8; nt++)
            bf[nt] = w2f2[(ku * 16 + wc * 8 + nt) * 32 + lane];
        uint32_t a[2][4];
        #pragma unroll
        for (int mt = 0; mt < 2; mt++) {
            int row = wr * 32 + mt * 16 + (lane & 15);
            int gk = ku * 2 + (lane >> 4);
            ldsm4(a[mt][0], a[mt][1], a[mt][2], a[mt][3],
                  sb + SM_BUF + row * 256 + ((gk ^ (row & 7)) << 4));
        }
        #pragma unroll
        for (int nt = 0; nt < 8; nt++)
            #pragma unroll
            for (int mt = 0; mt < 2; mt++)
                mma_f16(acc2[mt][nt], a[mt][0], a[mt][1], a[mt][2], a[mt][3],
                        bf[nt].x, bf[nt].y);
    }

    // ======== Epilogue 2: +b2, LayerNorm, residual, direct STG ========
    {
        const float* sb2 = (const float*)(smem + SM_B2);
        float s1[2][2], s2[2][2];
        #pragma unroll
        for (int mt = 0; mt < 2; mt++) { s1[mt][0] = s1[mt][1] = s2[mt][0] = s2[mt][1] = 0.f; }
        #pragma unroll
        for (int mt = 0; mt < 2; mt++)
            #pragma unroll
            for (int nt = 0; nt < 8; nt++) {
                int c0 = wc * 64 + nt * 8 + 2 * q;
                float y0 = acc2[mt][nt][0] + sb2[c0];
                float y1 = acc2[mt][nt][1] + sb2[c0 + 1];
                float y2 = acc2[mt][nt][2] + sb2[c0];
                float y3 = acc2[mt][nt][3] + sb2[c0 + 1];
                acc2[mt][nt][0] = y0; acc2[mt][nt][1] = y1;
                acc2[mt][nt][2] = y2; acc2[mt][nt][3] = y3;
                s1[mt][0] += y0 + y1; s2[mt][0] += y0 * y0 + y1 * y1;
                s1[mt][1] += y2 + y3; s2[mt][1] += y2 * y2 + y3 * y3;
            }
        #pragma unroll
        for (int mt = 0; mt < 2; mt++)
            #pragma unroll
            for (int h = 0; h < 2; h++) {
                s1[mt][h] += __shfl_xor_sync(0xffffffffu, s1[mt][h], 1);
                s1[mt][h] += __shfl_xor_sync(0xffffffffu, s1[mt][h], 2);
                s2[mt][h] += __shfl_xor_sync(0xffffffffu, s2[mt][h], 1);
                s2[mt][h] += __shfl_xor_sync(0xffffffffu, s2[mt][h], 2);
            }
        float* red1 = (float*)(smem + SM_RED);
        float* red2 = red1 + 256;
        if (q == 0) {
            #pragma unroll
            for (int mt = 0; mt < 2; mt++) {
                int rl = wr * 32 + mt * 16 + rq;
                red1[wc * 128 + rl]     = s1[mt][0];
                red2[wc * 128 + rl]     = s2[mt][0];
                red1[wc * 128 + rl + 8] = s1[mt][1];
                red2[wc * 128 + rl + 8] = s2[mt][1];
            }
        }
        __syncthreads();
        const float* sg  = (const float*)(smem + SM_GAMMA);
        const float* sbt = (const float*)(smem + SM_BETA);
        #pragma unroll
        for (int mt = 0; mt < 2; mt++)
            #pragma unroll
            for (int h = 0; h < 2; h++) {
                int r = wr * 32 + mt * 16 + rq + h * 8;
                float S1 = red1[r] + red1[128 + r];
                float S2 = red2[r] + red2[128 + r];
                float mu = S1 * (1.f / 128.f);
                float rs = rsqrtf(S2 * (1.f / 128.f) - mu * mu + LN_EPS);
                if (r < valid) {
                    const size_t e = (size_t)(e0 + r);
                    #pragma unroll
                    for (int nt = 0; nt < 8; nt++) {
                        int c0 = wc * 64 + nt * 8 + 2 * q;
                        float2 ef = *(const float2*)(efeat + e * DD + c0);
                        float2 o;
                        o.x = (acc2[mt][nt][2 * h]     - mu) * rs * sg[c0]     + sbt[c0]     + ef.x;
                        o.y = (acc2[mt][nt][2 * h + 1] - mu) * rs * sg[c0 + 1] + sbt[c0 + 1] + ef.y;
                        *(float2*)(out + e * DD + c0) = o;
                    }
                }
            }
    }
}

extern "C" void kernel_launch(void* const* d_in, const int* in_sizes, int n_in,
                              void* d_out, int out_size) {
    const float* efeat = (const float*)d_in[0];
    const float* nfeat = (const float*)d_in[1];
    const void*  src   = d_in[2];
    const void*  dst   = d_in[3];
    const float* w1    = (const float*)d_in[4];
    const float* b1    = (const float*)d_in[5];
    const float* w2    = (const float*)d_in[6];
    const float* b2    = (const float*)d_in[7];
    const float* gamma = (const float*)d_in[8];
    const float* beta  = (const float*)d_in[9];
    float* out = (float*)d_out;

    cudaFuncSetAttribute(fused_mma_kernel,
                         cudaFuncAttributeMaxDynamicSharedMemorySize, SMEM_TOTAL);
    cudaFuncSetAttribute(node_proj_kernel,
                         cudaFuncAttributeMaxDynamicSharedMemorySize, SMEM_TOTAL);

    prep_weights_kernel<<<256, 256>>>(w1, w2, src);
    node_proj_kernel<<<dim3(NPAD / TILE_M, 2), THREADS, SMEM_TOTAL>>>(nfeat);
    const long long need = (long long)EN * DD + (long long)NN * DD;
    if ((long long)out_size >= need) {
        int n4 = NN * DD / 4;
        copy_nfeat_kernel<<<(n4 + 255) / 256, 256>>>(
            (const float4*)nfeat, (float4*)(out + (size_t)EN * DD), n4);
    }
    fused_mma_kernel<<<NCTAS, THREADS, SMEM_TOTAL>>>(
        efeat, nfeat, src, dst, b1, b2, gamma, beta, out);
}

// round 17
// speedup vs baseline: 1.3766x; 1.0457x over previous
#include <cuda_runtime.h>
#include <cuda_fp16.h>
#include <cstdint>

#define EN 500000
#define NN 100000
#define NPAD 100096
#define DD 128
#define LN_EPS 1e-5f
#define TILE_M 128
#define NCTAS 3907
#define THREADS 256

// SMEM map
#define SM_B1    0
#define SM_B2    512
#define SM_GAMMA 1024
#define SM_BETA  1536
#define SM_SRC   2048
#define SM_DST   2560
#define SM_A     4096        // 32KB fp16 A tile (row*256B, granule-swizzled)
#define SM_H     36864       // 32KB fp16 H tile
#define SM_RED   69632       // 2KB reductions
#define SMEM_TOTAL 71680

__device__ int g_idx64;
// fragment-ordered fp16 weights: block 0=w1a, 1=w1b, 2=w1c, 3=w2
__device__ __half g_wf[4 * 16384];
__device__ float g_PQ[2ll * NPAD * 128];   // P (src proj), Q (dst proj)

// ---------------- helpers ----------------
__device__ __forceinline__ uint32_t smem_u32(const void* p) {
    uint32_t a;
    asm("{ .reg .u64 t; cvta.to.shared.u64 t, %1; cvt.u32.u64 %0, t; }" : "=r"(a) : "l"(p));
    return a;
}
__device__ __forceinline__ uint32_t pack_h2(float x, float y) {
    __half2 h = __floats2half2_rn(x, y);
    return *(uint32_t*)&h;
}
__device__ __forceinline__ void ldsm4(uint32_t& d0, uint32_t& d1, uint32_t& d2, uint32_t& d3,
                                      uint32_t addr) {
    asm volatile("ldmatrix.sync.aligned.m8n8.x4.shared.b16 {%0,%1,%2,%3}, [%4];"
        : "=r"(d0), "=r"(d1), "=r"(d2), "=r"(d3) : "r"(addr));
}
__device__ __forceinline__ void mma_f16(float* c, uint32_t a0, uint32_t a1, uint32_t a2,
                                        uint32_t a3, uint32_t b0, uint32_t b1) {
    asm volatile("mma.sync.aligned.m16n8k16.row.col.f32.f16.f16.f32 "
        "{%0,%1,%2,%3},{%4,%5,%6,%7},{%8,%9},{%0,%1,%2,%3};"
        : "+f"(c[0]), "+f"(c[1]), "+f"(c[2]), "+f"(c[3])
        : "r"(a0), "r"(a1), "r"(a2), "r"(a3), "r"(b0), "r"(b1));
}

// ---------------- prep kernel: detect + fragment-ordered fp16 weight images ----------------
__global__ void prep_weights_kernel(const float* __restrict__ w1,
                                    const float* __restrict__ w2,
                                    const void* __restrict__ src) {
    int i = blockIdx.x * blockDim.x + threadIdx.x;   // 0..65535
    if (i == 0) {
        const long long* p = (const long long*)src;
        int ok = 1;
        #pragma unroll
        for (int t = 0; t < 32; t++) {
            long long v = p[t];
            if (v < 0 || v >= (long long)NN) ok = 0;
        }
        g_idx64 = ok;
    }
    int b = i >> 14, t = i & 16383;
    int h = t & 1, r = (t >> 1) & 1, lane = (t >> 2) & 31, s = t >> 7;
    int nt = s & 15, ku = s >> 4;
    int k = ku * 16 + (lane & 3) * 2 + h + r * 8;
    int n = nt * 8 + (lane >> 2);
    float v = (b < 3) ? w1[(size_t)(b * 128 + k) * 128 + n]
                      : w2[(size_t)k * 128 + n];
    g_wf[b * 16384 + s * 128 + lane * 4 + r * 2 + h] = __float2half_rn(v);
}

__global__ void copy_nfeat_kernel(const float4* __restrict__ in,
                                  float4* __restrict__ out, int n4) {
    int i = blockIdx.x * blockDim.x + threadIdx.x;
    if (i < n4) out[i] = in[i];
}

// ---------------- node projection: P = nfeat@w1b, Q = nfeat@w1c (one nfeat load) ----------------
__global__ __launch_bounds__(THREADS, 2) void node_proj_kernel(
    const float* __restrict__ nfeat)
{
    extern __shared__ __align__(1024) char smem[];
    const uint32_t sb = smem_u32(smem);
    const int tid = threadIdx.x;
    const int lane = tid & 31;
    const int wr = (tid >> 5) & 3, wc = tid >> 7;
    const int n0 = blockIdx.x * TILE_M;
    const int q = lane & 3, rq = lane >> 2;

    // A prep: nfeat fp32 -> fp16 swizzled smem
    {
        const int rr = tid >> 1, ch = tid & 1;
        const float* rp = nfeat + (size_t)min(n0 + rr, NN - 1) * DD + ch * 64;
        #pragma unroll
        for (int j = 0; j < 8; j++) {
            float4 lo = *(const float4*)(rp + j * 8);
            float4 hi = *(const float4*)(rp + j * 8 + 4);
            uint4 pk;
            pk.x = pack_h2(lo.x, lo.y); pk.y = pack_h2(lo.z, lo.w);
            pk.z = pack_h2(hi.x, hi.y); pk.w = pack_h2(hi.z, hi.w);
            int g = ch * 8 + j;
            *(uint4*)(smem + SM_A + rr * 256 + ((g ^ (rr & 7)) << 4)) = pk;
        }
    }
    __syncthreads();

    #pragma unroll
    for (int which = 0; which < 2; which++) {
        float acc[2][8][4];
        #pragma unroll
        for (int mt = 0; mt < 2; mt++)
            #pragma unroll
            for (int nt = 0; nt < 8; nt++)
                #pragma unroll
                for (int j = 0; j < 4; j++) acc[mt][nt][j] = 0.f;

        const uint2* wf = (const uint2*)(g_wf + (1 + which) * 16384);
        #pragma unroll
        for (int ku = 0; ku < 8; ku++) {
            uint2 bf[8];
            #pragma unroll
            for (int nt = 0; nt < 8; nt++)
                bf[nt] = wf[(ku * 16 + wc * 8 + nt) * 32 + lane];
            uint32_t a[2][4];
            #pragma unroll
            for (int mt = 0; mt < 2; mt++) {
                int row = wr * 32 + mt * 16 + (lane & 15);
                int gk = ku * 2 + (lane >> 4);
                ldsm4(a[mt][0], a[mt][1], a[mt][2], a[mt][3],
                      sb + SM_A + row * 256 + ((gk ^ (row & 7)) << 4));
            }
            #pragma unroll
            for (int nt = 0; nt < 8; nt++)
                #pragma unroll
                for (int mt = 0; mt < 2; mt++)
                    mma_f16(acc[mt][nt], a[mt][0], a[mt][1], a[mt][2], a[mt][3],
                            bf[nt].x, bf[nt].y);
        }

        float* dst = g_PQ + (size_t)which * NPAD * 128;
        #pragma unroll
        for (int mt = 0; mt < 2; mt++) {
            int rl = wr * 32 + mt * 16 + rq, rh = rl + 8;
            int nl = n0 + rl, nh = n0 + rh;
            #pragma unroll
            for (int nt = 0; nt < 8; nt++) {
                int c0 = wc * 64 + nt * 8 + 2 * q;
                if (nl < NN) *(float2*)(dst + (size_t)nl * 128 + c0) =
                    make_float2(acc[mt][nt][0], acc[mt][nt][1]);
                if (nh < NN) *(float2*)(dst + (size_t)nh * 128 + c0) =
                    make_float2(acc[mt][nt][2], acc[mt][nt][3]);
            }
        }
    }
}

// ---------------- main fused edge kernel ----------------
__global__ __launch_bounds__(THREADS, 2) void fused_mma_kernel(
    const float* __restrict__ efeat,
    const void* __restrict__ src_raw, const void* __restrict__ dst_raw,
    const float* __restrict__ b1, const float* __restrict__ b2,
    const float* __restrict__ gamma, const float* __restrict__ beta,
    float* __restrict__ out)
{
    extern __shared__ __align__(1024) char smem[];
    const uint32_t sb = smem_u32(smem);
    const int tid = threadIdx.x;
    const int wid = tid >> 5, lane = tid & 31;
    const int wr = wid & 3, wc = wid >> 2;
    const int e0 = blockIdx.x * TILE_M;
    const int valid = min(TILE_M, EN - e0);
    const int q = lane & 3, rq = lane >> 2;

    // A prep: efeat fp32 -> fp16 swizzled smem (LDGs start immediately)
    {
        const int rr = tid >> 1, ch = tid & 1;
        const float* rp = efeat + (size_t)min(e0 + rr, EN - 1) * DD + ch * 64;
        #pragma unroll
        for (int j = 0; j < 8; j++) {
            float4 lo = *(const float4*)(rp + j * 8);
            float4 hi = *(const float4*)(rp + j * 8 + 4);
            uint4 pk;
            pk.x = pack_h2(lo.x, lo.y); pk.y = pack_h2(lo.z, lo.w);
            pk.z = pack_h2(hi.x, hi.y); pk.w = pack_h2(hi.z, hi.w);
            int g = ch * 8 + j;
            *(uint4*)(smem + SM_A + rr * 256 + ((g ^ (rr & 7)) << 4)) = pk;
        }
    }
    if (tid < 128) {
        ((float*)(smem + SM_B1))[tid]    = b1[tid];
        ((float*)(smem + SM_B2))[tid]    = b2[tid];
        ((float*)(smem + SM_GAMMA))[tid] = gamma[tid];
        ((float*)(smem + SM_BETA))[tid]  = beta[tid];
        int e = min(e0 + tid, EN - 1);
        int s, d;
        if (g_idx64) {
            s = (int)((const long long*)src_raw)[e];
            d = (int)((const long long*)dst_raw)[e];
        } else {
            s = ((const int*)src_raw)[e];
            d = ((const int*)dst_raw)[e];
        }
        ((int*)(smem + SM_SRC))[tid] = s;
        ((int*)(smem + SM_DST))[tid] = d;
    }
    __syncthreads();

    const int* ssrc = (const int*)(smem + SM_SRC);
    const int* sdst = (const int*)(smem + SM_DST);

    // ======== GEMM1': efeat @ w1a (8 k16 units, frag-B LDG, A via ldsm) ========
    {
        float acc[2][8][4];
        #pragma unroll
        for (int mt = 0; mt < 2; mt++)
            #pragma unroll
            for (int nt = 0; nt < 8; nt++)
                #pragma unroll
                for (int j = 0; j < 4; j++) acc[mt][nt][j] = 0.f;

        const uint2* wf0 = (const uint2*)g_wf;
        #pragma unroll
        for (int ku = 0; ku < 8; ku++) {
            uint2 bf[8];
            #pragma unroll
            for (int nt = 0; nt < 8; nt++)
                bf[nt] = wf0[(ku * 16 + wc * 8 + nt) * 32 + lane];
            uint32_t a[2][4];
            #pragma unroll
            for (int mt = 0; mt < 2; mt++) {
                int row = wr * 32 + mt * 16 + (lane & 15);
                int gk = ku * 2 + (lane >> 4);
                ldsm4(a[mt][0], a[mt][1], a[mt][2], a[mt][3],
                      sb + SM_A + row * 256 + ((gk ^ (row & 7)) << 4));
            }
            #pragma unroll
            for (int nt = 0; nt < 8; nt++)
                #pragma unroll
                for (int mt = 0; mt < 2; mt++)
                    mma_f16(acc[mt][nt], a[mt][0], a[mt][1], a[mt][2], a[mt][3],
                            bf[nt].x, bf[nt].y);
        }

        // ======== gather-add node projections: acc += P[src] + Q[dst] ========
        const float* P = g_PQ;
        const float* Q = g_PQ + (size_t)NPAD * 128;
        #pragma unroll
        for (int mt = 0; mt < 2; mt++) {
            int rl = wr * 32 + mt * 16 + rq, rh = rl + 8;
            const float* ps0 = P + (size_t)ssrc[rl] * 128;
            const float* pd0 = Q + (size_t)sdst[rl] * 128;
            const float* ps1 = P + (size_t)ssrc[rh] * 128;
            const float* pd1 = Q + (size_t)sdst[rh] * 128;
            #pragma unroll
            for (int nt = 0; nt < 8; nt++) {
                int c0 = wc * 64 + nt * 8 + 2 * q;
                float2 a0 = *(const float2*)(ps0 + c0);
                float2 b0 = *(const float2*)(pd0 + c0);
                float2 a1 = *(const float2*)(ps1 + c0);
                float2 b1v = *(const float2*)(pd1 + c0);
                acc[mt][nt][0] += a0.x + b0.x;
                acc[mt][nt][1] += a0.y + b0.y;
                acc[mt][nt][2] += a1.x + b1v.x;
                acc[mt][nt][3] += a1.y + b1v.y;
            }
        }

        // ======== Epilogue 1: +b1, SiLU, fp16 -> H (separate region, no pre-barrier) ========
        const float* sb1 = (const float*)(smem + SM_B1);
        #pragma unroll
        for (int mt = 0; mt < 2; mt++) {
            int rl = wr * 32 + mt * 16 + rq, rh = rl + 8;
            #pragma unroll
            for (int nt = 0; nt < 8; nt++) {
                int c0 = wc * 64 + nt * 8 + 2 * q;
                float x0 = acc[mt][nt][0] + sb1[c0];
                float x1 = acc[mt][nt][1] + sb1[c0 + 1];
                float x2 = acc[mt][nt][2] + sb1[c0];
                float x3 = acc[mt][nt][3] + sb1[c0 + 1];
                float s0 = __fdividef(x0, 1.f + __expf(-x0));
                float s1 = __fdividef(x1, 1.f + __expf(-x1));
                float s2 = __fdividef(x2, 1.f + __expf(-x2));
                float s3 = __fdividef(x3, 1.f + __expf(-x3));
                int go = (((c0 >> 3) ^ (rl & 7)) << 4) + (c0 & 7) * 2;
                int gh = (((c0 >> 3) ^ (rh & 7)) << 4) + (c0 & 7) * 2;
                *(uint32_t*)(smem + SM_H + rl * 256 + go) = pack_h2(s0, s1);
                *(uint32_t*)(smem + SM_H + rh * 256 + gh) = pack_h2(s2, s3);
            }
        }
    }   // acc dies

    // ---- prefetch efeat residual while H settles ----
    float2 efr[2][2][8];
    #pragma unroll
    for (int mt = 0; mt < 2; mt++)
        #pragma unroll
        for (int h = 0; h < 2; h++) {
            int r = wr * 32 + mt * 16 + rq + h * 8;
            const float* ep = efeat + (size_t)min(e0 + r, EN - 1) * DD;
            #pragma unroll
            for (int nt = 0; nt < 8; nt++) {
                int c0 = wc * 64 + nt * 8 + 2 * q;
                efr[mt][h][nt] = *(const float2*)(ep + c0);
            }
        }
    __syncthreads();       // H complete (partner warp wrote other column half)

    // ======== GEMM2: D2 = H @ w2 (frag-B LDG) ========
    float acc2[2][8][4];
    #pragma unroll
    for (int mt = 0; mt < 2; mt++)
        #pragma unroll
        for (int nt = 0; nt < 8; nt++)
            #pragma unroll
            for (int j = 0; j < 4; j++) acc2[mt][nt][j] = 0.f;

    const uint2* wf3 = (const uint2*)(g_wf + 3 * 16384);
    #pragma unroll
    for (int ku = 0; ku < 8; ku++) {
        uint2 bf[8];
        #pragma unroll
        for (int nt = 0; nt < 8; nt++)
            bf[nt] = wf3[(ku * 16 + wc * 8 + nt) * 32 + lane];
        uint32_t a[2][4];
        #pragma unroll
        for (int mt = 0; mt < 2; mt++) {
            int row = wr * 32 + mt * 16 + (lane & 15);
            int gk = ku * 2 + (lane >> 4);
            ldsm4(a[mt][0], a[mt][1], a[mt][2], a[mt][3],
                  sb + SM_H + row * 256 + ((gk ^ (row & 7)) << 4));
        }
        #pragma unroll
        for (int nt = 0; nt < 8; nt++)
            #pragma unroll
            for (int mt = 0; mt < 2; mt++)
                mma_f16(acc2[mt][nt], a[mt][0], a[mt][1], a[mt][2], a[mt][3],
                        bf[nt].x, bf[nt].y);
    }

    // ======== Epilogue 2: +b2, LayerNorm, residual (prefetched), direct STG ========
    {
        const float* sb2 = (const float*)(smem + SM_B2);
        float s1[2][2], s2[2][2];
        #pragma unroll
        for (int mt = 0; mt < 2; mt++) { s1[mt][0] = s1[mt][1] = s2[mt][0] = s2[mt][1] = 0.f; }
        #pragma unroll
        for (int mt = 0; mt < 2; mt++)
            #pragma unroll
            for (int nt = 0; nt < 8; nt++) {
                int c0 = wc * 64 + nt * 8 + 2 * q;
                float y0 = acc2[mt][nt][0] + sb2[c0];
                float y1 = acc2[mt][nt][1] + sb2[c0 + 1];
                float y2 = acc2[mt][nt][2] + sb2[c0];
                float y3 = acc2[mt][nt][3] + sb2[c0 + 1];
                acc2[mt][nt][0] = y0; acc2[mt][nt][1] = y1;
                acc2[mt][nt][2] = y2; acc2[mt][nt][3] = y3;
                s1[mt][0] += y0 + y1; s2[mt][0] += y0 * y0 + y1 * y1;
                s1[mt][1] += y2 + y3; s2[mt][1] += y2 * y2 + y3 * y3;
            }
        #pragma unroll
        for (int mt = 0; mt < 2; mt++)
            #pragma unroll
            for (int h = 0; h < 2; h++) {
                s1[mt][h] += __shfl_xor_sync(0xffffffffu, s1[mt][h], 1);
                s1[mt][h] += __shfl_xor_sync(0xffffffffu, s1[mt][h], 2);
                s2[mt][h] += __shfl_xor_sync(0xffffffffu, s2[mt][h], 1);
                s2[mt][h] += __shfl_xor_sync(0xffffffffu, s2[mt][h], 2);
            }
        float* red1 = (float*)(smem + SM_RED);
        float* red2 = red1 + 256;
        if (q == 0) {
            #pragma unroll
            for (int mt = 0; mt < 2; mt++) {
                int rl = wr * 32 + mt * 16 + rq;
                red1[wc * 128 + rl]     = s1[mt][0];
                red2[wc * 128 + rl]     = s2[mt][0];
                red1[wc * 128 + rl + 8] = s1[mt][1];
                red2[wc * 128 + rl + 8] = s2[mt][1];
            }
        }
        __syncthreads();
        const float* sg  = (const float*)(smem + SM_GAMMA);
        const float* sbt = (const float*)(smem + SM_BETA);
        #pragma unroll
        for (int mt = 0; mt < 2; mt++)
            #pragma unroll
            for (int h = 0; h < 2; h++) {
                int r = wr * 32 + mt * 16 + rq + h * 8;
                float S1 = red1[r] + red1[128 + r];
                float S2 = red2[r] + red2[128 + r];
                float mu = S1 * (1.f / 128.f);
                float rs = rsqrtf(S2 * (1.f / 128.f) - mu * mu + LN_EPS);
                if (r < valid) {
                    const size_t e = (size_t)(e0 + r);
                    #pragma unroll
                    for (int nt = 0; nt < 8; nt++) {
                        int c0 = wc * 64 + nt * 8 + 2 * q;
                        float2 ef = efr[mt][h][nt];
                        float2 o;
                        o.x = (acc2[mt][nt][2 * h]     - mu) * rs * sg[c0]     + sbt[c0]     + ef.x;
                        o.y = (acc2[mt][nt][2 * h + 1] - mu) * rs * sg[c0 + 1] + sbt[c0 + 1] + ef.y;
                        *(float2*)(out + e * DD + c0) = o;
                    }
                }
            }
    }
}

extern "C" void kernel_launch(void* const* d_in, const int* in_sizes, int n_in,
                              void* d_out, int out_size) {
    const float* efeat = (const float*)d_in[0];
    const float* nfeat = (const float*)d_in[1];
    const void*  src   = d_in[2];
    const void*  dst   = d_in[3];
    const float* w1    = (const float*)d_in[4];
    const float* b1    = (const float*)d_in[5];
    const float* w2    = (const float*)d_in[6];
    const float* b2    = (const float*)d_in[7];
    const float* gamma = (const float*)d_in[8];
    const float* beta  = (const float*)d_in[9];
    float* out = (float*)d_out;

    cudaFuncSetAttribute(fused_mma_kernel,
                         cudaFuncAttributeMaxDynamicSharedMemorySize, SMEM_TOTAL);
    cudaFuncSetAttribute(node_proj_kernel,
                         cudaFuncAttributeMaxDynamicSharedMemorySize, SMEM_TOTAL);

    prep_weights_kernel<<<256, 256>>>(w1, w2, src);
    node_proj_kernel<<<NPAD / TILE_M, THREADS, SMEM_TOTAL>>>(nfeat);
    const long long need = (long long)EN * DD + (long long)NN * DD;
    if ((long long)out_size >= need) {
        int n4 = NN * DD / 4;
        copy_nfeat_kernel<<<(n4 + 255) / 256, 256>>>(
            (const float4*)nfeat, (float4*)(out + (size_t)EN * DD), n4);
    }
    fused_mma_kernel<<<NCTAS, THREADS, SMEM_TOTAL>>>(
        efeat, src, dst, b1, b2, gamma, beta, out);
}